// round 4
// baseline (speedup 1.0000x reference)
#include <cuda_runtime.h>

#define NNODES 100000
#define NEDGES 1600000
#define NB1 ((NNODES + 255) / 256)   // 391 scan blocks

// ---------------- scratch (device globals: allocation-free) ----------------
// NOTE: these are ONLY ever referenced from device code (never passed as
// kernel arguments from host — that address is a host shadow symbol and on
// GB300/ATS writes there silently succeed into host memory).
__device__ int   g_is64;                 // edge_index dtype flag
__device__ float g_deg[NNODES];
__device__ float g_dis[NNODES];
__device__ int   g_hist[NNODES];
__device__ int   g_row[NNODES + 1];      // CSR row_ptr (by dst)
__device__ int   g_cursor[NNODES];
__device__ int   g_bsums[NB1];
__device__ int2  g_edge[NEDGES];         // {src, norm-as-bits}, sorted by dst
__device__ float g_h1[(size_t)NNODES * 128];  // x @ W1
__device__ float g_a1[(size_t)NNODES * 128];  // relu(aggregate1)  (layer-2 input)
__device__ float g_h2[(size_t)NNODES * 64];   // a1 @ W2

// ---------------- edge_index dtype detection ----------------
// int64 values < 2^31 => every odd 32-bit word is 0. int32 node ids => not all zero.
__global__ void k_detect(const int* __restrict__ ei_raw) {
    if (threadIdx.x == 0 && blockIdx.x == 0) {
        int is64 = 1;
        for (int i = 1; i < 512; i += 2)
            if (ei_raw[i] != 0) { is64 = 0; break; }
        g_is64 = is64;
    }
}

__device__ __forceinline__ void load_edge(const void* __restrict__ ei, int e,
                                          int& s, int& d) {
    if (g_is64) {
        const long long* p = (const long long*)ei;
        s = (int)p[e];
        d = (int)p[NEDGES + e];
    } else {
        const int* p = (const int*)ei;
        s = p[e];
        d = p[NEDGES + e];
    }
}

// ---------------- degree / histogram ----------------
__global__ void k_init() {
    int i = blockIdx.x * 256 + threadIdx.x;
    if (i < NNODES) { g_deg[i] = 1.0f; g_hist[i] = 0; }   // self-loop weight 1
}

__global__ void k_deg(const void* __restrict__ ei, const float* __restrict__ ew) {
    int e = blockIdx.x * 256 + threadIdx.x;
    if (e < NEDGES) {
        int s, d;
        load_edge(ei, e, s, d);
        atomicAdd(&g_deg[d], ew[e]);
        atomicAdd(&g_hist[d], 1);
    }
}

__global__ void k_dis() {
    int i = blockIdx.x * 256 + threadIdx.x;
    if (i < NNODES) g_dis[i] = rsqrtf(g_deg[i]);   // deg >= 1 always (self-loop)
}

// ---------------- exclusive scan of g_hist -> g_row ----------------
__global__ void k_scan1() {
    __shared__ int sh[256];
    int i = blockIdx.x * 256 + threadIdx.x;
    int tid = threadIdx.x;
    int v = (i < NNODES) ? g_hist[i] : 0;
    sh[tid] = v; __syncthreads();
    for (int off = 1; off < 256; off <<= 1) {
        int t = (tid >= off) ? sh[tid - off] : 0;
        __syncthreads(); sh[tid] += t; __syncthreads();
    }
    if (i < NNODES) g_row[i] = sh[tid] - v;           // block-local exclusive
    if (tid == 255) g_bsums[blockIdx.x] = sh[tid];    // block total
}

__global__ void k_scan2() {   // single block, 512 threads >= NB1
    __shared__ int sh[512];
    int tid = threadIdx.x;
    int v = (tid < NB1) ? g_bsums[tid] : 0;
    sh[tid] = v; __syncthreads();
    for (int off = 1; off < 512; off <<= 1) {
        int t = (tid >= off) ? sh[tid - off] : 0;
        __syncthreads(); sh[tid] += t; __syncthreads();
    }
    if (tid < NB1) g_bsums[tid] = sh[tid] - v;        // exclusive block offsets
}

__global__ void k_scan3() {
    int i = blockIdx.x * 256 + threadIdx.x;
    if (i < NNODES) {
        int r = g_row[i] + g_bsums[blockIdx.x];
        g_row[i] = r;
        g_cursor[i] = r;
        if (i == 0) g_row[NNODES] = NEDGES;
    }
}

// ---------------- scatter edges into dst-sorted CSR order ----------------
__global__ void k_sort(const void* __restrict__ ei, const float* __restrict__ ew) {
    int e = blockIdx.x * 256 + threadIdx.x;
    if (e < NEDGES) {
        int s, d;
        load_edge(ei, e, s, d);
        float nrm = g_dis[s] * ew[e] * g_dis[d];
        int pos = atomicAdd(&g_cursor[d], 1);
        g_edge[pos] = make_int2(s, __float_as_int(nrm));
    }
}

// ---------------- GEMM (M x 128) @ (128 x NCOL) -> H (device-global) --------
// LAYER==1: X = Xin (harness x), H = g_h1.  LAYER==2: X = g_a1, H = g_h2.
template<int NCOL, int LAYER>
__global__ __launch_bounds__(256) void gemm(
    const float* __restrict__ Xin, const float* __restrict__ W, int M)
{
    constexpr int TC = NCOL / 16;   // cols per thread (8 or 4)
    constexpr int BK = 32;
    __shared__ float Xs[128 * BK];
    __shared__ float Ws[BK * NCOL];

    const float* __restrict__ X = (LAYER == 1) ? Xin : g_a1;
    float* __restrict__ H = (LAYER == 1) ? g_h1 : g_h2;

    const int tid  = threadIdx.x;
    const int row0 = blockIdx.x * 128;
    const int tc   = tid & 15;
    const int tr   = tid >> 4;

    float acc[8][TC];
#pragma unroll
    for (int i = 0; i < 8; i++)
#pragma unroll
        for (int j = 0; j < TC; j++) acc[i][j] = 0.f;

    for (int kt = 0; kt < 128 / BK; kt++) {
#pragma unroll
        for (int idx = tid; idx < 128 * BK / 4; idx += 256) {
            int r = idx >> 3, c4 = idx & 7;
            float4 v = make_float4(0.f, 0.f, 0.f, 0.f);
            int gr = row0 + r;
            if (gr < M)
                v = reinterpret_cast<const float4*>(X)[(size_t)gr * 32 + kt * (BK / 4) + c4];
            reinterpret_cast<float4*>(Xs)[idx] = v;
        }
#pragma unroll
        for (int idx = tid; idx < BK * NCOL / 4; idx += 256)
            reinterpret_cast<float4*>(Ws)[idx] =
                reinterpret_cast<const float4*>(W)[kt * (BK * NCOL / 4) + idx];
        __syncthreads();

#pragma unroll
        for (int kk = 0; kk < BK; kk++) {
            float a[8];
#pragma unroll
            for (int i = 0; i < 8; i++) a[i] = Xs[(tr * 8 + i) * BK + kk];
            float b[TC];
#pragma unroll
            for (int j = 0; j < TC; j += 4) {
                float4 bv = *reinterpret_cast<const float4*>(Ws + kk * NCOL + tc * TC + j);
                b[j] = bv.x; b[j + 1] = bv.y; b[j + 2] = bv.z; b[j + 3] = bv.w;
            }
#pragma unroll
            for (int i = 0; i < 8; i++)
#pragma unroll
                for (int j = 0; j < TC; j++) acc[i][j] = fmaf(a[i], b[j], acc[i][j]);
        }
        __syncthreads();
    }

#pragma unroll
    for (int i = 0; i < 8; i++) {
        int r = row0 + tr * 8 + i;
        if (r >= M) continue;
#pragma unroll
        for (int j = 0; j < TC; j += 4) {
            float4 hv = make_float4(acc[i][j], acc[i][j + 1], acc[i][j + 2], acc[i][j + 3]);
            reinterpret_cast<float4*>(H)[((size_t)r * NCOL + tc * TC + j) >> 2] = hv;
        }
    }
}

// ---------------- segmented aggregation: one warp per dst node ----------------
// a1[d] = relu( b1 + dis[d]^2*h1[d] + sum_e norm_e * h1[src_e] ),  C=128 (float4/lane)
__global__ __launch_bounds__(256) void agg1(const float* __restrict__ bias) {
    int w = (blockIdx.x * 256 + threadIdx.x) >> 5;
    int lane = threadIdx.x & 31;
    if (w >= NNODES) return;
    const float4* H = reinterpret_cast<const float4*>(g_h1);

    int beg = g_row[w], end = g_row[w + 1];
    float ds = g_dis[w];
    float s2 = ds * ds;
    float4 h = H[(size_t)w * 32 + lane];
    float4 acc = make_float4(s2 * h.x, s2 * h.y, s2 * h.z, s2 * h.w);

    for (int e = beg; e < end; e++) {
        int2 md = g_edge[e];
        float nm = __int_as_float(md.y);
        float4 hv = H[(size_t)md.x * 32 + lane];
        acc.x = fmaf(nm, hv.x, acc.x);
        acc.y = fmaf(nm, hv.y, acc.y);
        acc.z = fmaf(nm, hv.z, acc.z);
        acc.w = fmaf(nm, hv.w, acc.w);
    }
    float4 bv = reinterpret_cast<const float4*>(bias)[lane];
    acc.x = fmaxf(acc.x + bv.x, 0.f);
    acc.y = fmaxf(acc.y + bv.y, 0.f);
    acc.z = fmaxf(acc.z + bv.z, 0.f);
    acc.w = fmaxf(acc.w + bv.w, 0.f);
    reinterpret_cast<float4*>(g_a1)[(size_t)w * 32 + lane] = acc;
}

// out[d] = b2 + dis[d]^2*h2[d] + sum_e norm_e * h2[src_e],  C=64 (float2/lane)
__global__ __launch_bounds__(256) void agg2(const float* __restrict__ bias,
                                            float* __restrict__ out) {
    int w = (blockIdx.x * 256 + threadIdx.x) >> 5;
    int lane = threadIdx.x & 31;
    if (w >= NNODES) return;
    const float2* H = reinterpret_cast<const float2*>(g_h2);

    int beg = g_row[w], end = g_row[w + 1];
    float ds = g_dis[w];
    float s2 = ds * ds;
    float2 h = H[(size_t)w * 32 + lane];
    float2 acc = make_float2(s2 * h.x, s2 * h.y);

    for (int e = beg; e < end; e++) {
        int2 md = g_edge[e];
        float nm = __int_as_float(md.y);
        float2 hv = H[(size_t)md.x * 32 + lane];
        acc.x = fmaf(nm, hv.x, acc.x);
        acc.y = fmaf(nm, hv.y, acc.y);
    }
    float2 bv = reinterpret_cast<const float2*>(bias)[lane];
    acc.x += bv.x;
    acc.y += bv.y;
    reinterpret_cast<float2*>(out)[(size_t)w * 32 + lane] = acc;
}

// ---------------- launch ----------------
extern "C" void kernel_launch(void* const* d_in, const int* in_sizes, int n_in,
                              void* d_out, int out_size)
{
    const float* x  = (const float*)d_in[0];
    const void*  ei = d_in[1];
    const float* ew = (const float*)d_in[2];
    const float* W1 = (const float*)d_in[3];
    const float* b1 = (const float*)d_in[4];
    const float* W2 = (const float*)d_in[5];
    const float* b2 = (const float*)d_in[6];
    float* out = (float*)d_out;

    const int nb_nodes = (NNODES + 255) / 256;   // = NB1
    const int nb_edges = (NEDGES + 255) / 256;
    const int nb_rows  = (NNODES + 127) / 128;
    const int nb_warps = (NNODES * 32 + 255) / 256;

    k_detect<<<1, 32>>>((const int*)ei);
    k_init<<<nb_nodes, 256>>>();
    k_deg<<<nb_edges, 256>>>(ei, ew);
    k_dis<<<nb_nodes, 256>>>();
    k_scan1<<<nb_nodes, 256>>>();
    k_scan2<<<1, 512>>>();
    k_scan3<<<nb_nodes, 256>>>();
    k_sort<<<nb_edges, 256>>>(ei, ew);

    gemm<128, 1><<<nb_rows, 256>>>(x, W1, NNODES);
    agg1<<<nb_warps, 256>>>(b1);

    gemm<64, 2><<<nb_rows, 256>>>(nullptr, W2, NNODES);
    agg2<<<nb_warps, 256>>>(b2, out);
}

// round 5
// speedup vs baseline: 1.0883x; 1.0883x over previous
#include <cuda_runtime.h>

#define NNODES 100000
#define NEDGES 1600000
#define NB1 ((NNODES + 255) / 256)   // 391 scan blocks

typedef unsigned long long ull;

// ---------------- scratch (device globals: allocation-free) ----------------
// ONLY referenced from device code (host-side &global is a shadow symbol).
__device__ int   g_is64;
__device__ float g_deg[NNODES];
__device__ float g_dis[NNODES];
__device__ int   g_hist[NNODES];
__device__ int   g_row[NNODES + 1];
__device__ int   g_cursor[NNODES];
__device__ int   g_bsums[NB1];
__device__ int2  g_edge[NEDGES];              // {src, norm-bits}, dst-sorted
__device__ float g_h1[(size_t)NNODES * 128];
__device__ float g_a1[(size_t)NNODES * 128];
__device__ float g_h2[(size_t)NNODES * 64];

// ---------------- f32x2 packed-math helpers ----------------
__device__ __forceinline__ ull pk2(float lo, float hi) {
    ull r;
    asm("mov.b64 %0, {%1,%2};" : "=l"(r)
        : "r"(__float_as_uint(lo)), "r"(__float_as_uint(hi)));
    return r;
}
__device__ __forceinline__ ull dup2(float v) {
    ull r;
    asm("mov.b64 %0, {%1,%1};" : "=l"(r) : "r"(__float_as_uint(v)));
    return r;
}
__device__ __forceinline__ ull fma2(ull a, ull b, ull c) {
    ull d;
    asm("fma.rn.f32x2 %0, %1, %2, %3;" : "=l"(d) : "l"(a), "l"(b), "l"(c));
    return d;
}
__device__ __forceinline__ float lo32(ull v) { return __uint_as_float((unsigned)v); }
__device__ __forceinline__ float hi32(ull v) { return __uint_as_float((unsigned)(v >> 32)); }

// ---------------- edge_index dtype detection (parallel) ----------------
__global__ void k_detect(const int* __restrict__ ei_raw) {
    int bad = 0;
    for (int i = threadIdx.x; i < 2048; i += 256)
        bad |= (ei_raw[2 * i + 1] != 0);      // int64 high words all zero
    bad = __syncthreads_or(bad);
    if (threadIdx.x == 0) g_is64 = !bad;
}

__device__ __forceinline__ void load_edge(const void* __restrict__ ei, int e,
                                          int& s, int& d) {
    if (g_is64) {
        const long long* p = (const long long*)ei;
        s = (int)p[e];
        d = (int)p[NEDGES + e];
    } else {
        const int* p = (const int*)ei;
        s = p[e];
        d = p[NEDGES + e];
    }
}

// ---------------- degree / histogram ----------------
__global__ void k_init() {
    int i = blockIdx.x * 256 + threadIdx.x;
    if (i < NNODES) { g_deg[i] = 1.0f; g_hist[i] = 0; }   // self-loop weight 1
}

__global__ void k_deg(const void* __restrict__ ei, const float* __restrict__ ew) {
    int e = blockIdx.x * 256 + threadIdx.x;
    if (e < NEDGES) {
        int s, d;
        load_edge(ei, e, s, d);
        atomicAdd(&g_deg[d], ew[e]);
        atomicAdd(&g_hist[d], 1);
    }
}

// ---------------- scan (hist -> row_ptr), fused dis ----------------
__global__ void k_scan1() {
    __shared__ int sh[256];
    int i = blockIdx.x * 256 + threadIdx.x;
    int tid = threadIdx.x;
    if (i < NNODES) g_dis[i] = rsqrtf(g_deg[i]);     // deg >= 1 always
    int v = (i < NNODES) ? g_hist[i] : 0;
    sh[tid] = v; __syncthreads();
    for (int off = 1; off < 256; off <<= 1) {
        int t = (tid >= off) ? sh[tid - off] : 0;
        __syncthreads(); sh[tid] += t; __syncthreads();
    }
    if (i < NNODES) g_row[i] = sh[tid] - v;
    if (tid == 255) g_bsums[blockIdx.x] = sh[tid];
}

__global__ void k_scan2() {   // single block, 512 >= NB1
    __shared__ int sh[512];
    int tid = threadIdx.x;
    int v = (tid < NB1) ? g_bsums[tid] : 0;
    sh[tid] = v; __syncthreads();
    for (int off = 1; off < 512; off <<= 1) {
        int t = (tid >= off) ? sh[tid - off] : 0;
        __syncthreads(); sh[tid] += t; __syncthreads();
    }
    if (tid < NB1) g_bsums[tid] = sh[tid] - v;
}

__global__ void k_scan3() {
    int i = blockIdx.x * 256 + threadIdx.x;
    if (i < NNODES) {
        int r = g_row[i] + g_bsums[blockIdx.x];
        g_row[i] = r;
        g_cursor[i] = r;
        if (i == 0) g_row[NNODES] = NEDGES;
    }
}

__global__ void k_sort(const void* __restrict__ ei, const float* __restrict__ ew) {
    int e = blockIdx.x * 256 + threadIdx.x;
    if (e < NEDGES) {
        int s, d;
        load_edge(ei, e, s, d);
        float nrm = g_dis[s] * ew[e] * g_dis[d];
        int pos = atomicAdd(&g_cursor[d], 1);
        g_edge[pos] = make_int2(s, __float_as_int(nrm));
    }
}

// ---------------- GEMM via packed f32x2: (M x 128) @ (128 x NCOL) ----------
// Row-pairs packed into 64-bit lanes. Xs stored k-major (transposed) so row
// pairs are contiguous; B values duplicated per kk via mov.b64.
template<int NCOL, int LAYER>
__global__ __launch_bounds__(256, 2) void gemm(
    const float* __restrict__ Xin, const float* __restrict__ W, int M)
{
    constexpr int TC = NCOL / 16;    // cols per thread (8 or 4)
    constexpr int BK = 32;
    constexpr int XSS = 132;         // padded stride (16B-aligned, low conflict)
    __shared__ __align__(16) float Xs[BK * XSS];
    __shared__ __align__(16) float Ws[BK * NCOL];

    const float* __restrict__ X = (LAYER == 1) ? Xin : g_a1;
    float* __restrict__ H = (LAYER == 1) ? g_h1 : g_h2;

    const int tid  = threadIdx.x;
    const int row0 = blockIdx.x * 128;
    const int tc   = tid & 15;
    const int tr   = tid >> 4;

    ull acc[4][TC];
#pragma unroll
    for (int p = 0; p < 4; p++)
#pragma unroll
        for (int j = 0; j < TC; j++) acc[p][j] = 0ull;

    for (int kt = 0; kt < 128 / BK; kt++) {
        // X tile (transpose into k-major smem)
#pragma unroll
        for (int idx = tid; idx < 128 * BK / 4; idx += 256) {
            int r = idx >> 3, c4 = idx & 7;
            float4 v = make_float4(0.f, 0.f, 0.f, 0.f);
            int gr = row0 + r;
            if (gr < M)
                v = reinterpret_cast<const float4*>(X)[(size_t)gr * 32 + kt * 8 + c4];
            int kk = c4 * 4;
            Xs[(kk + 0) * XSS + r] = v.x;
            Xs[(kk + 1) * XSS + r] = v.y;
            Xs[(kk + 2) * XSS + r] = v.z;
            Xs[(kk + 3) * XSS + r] = v.w;
        }
        // W tile (contiguous rows kt*BK .. +BK)
#pragma unroll
        for (int idx = tid; idx < BK * NCOL / 4; idx += 256)
            reinterpret_cast<float4*>(Ws)[idx] =
                reinterpret_cast<const float4*>(W)[kt * (BK * NCOL / 4) + idx];
        __syncthreads();

#pragma unroll
        for (int kk = 0; kk < BK; kk++) {
            // 8 rows as 4 packed pairs
            ulonglong2 la0 = *reinterpret_cast<const ulonglong2*>(&Xs[kk * XSS + tr * 8]);
            ulonglong2 la1 = *reinterpret_cast<const ulonglong2*>(&Xs[kk * XSS + tr * 8 + 4]);
            ull a[4] = { la0.x, la0.y, la1.x, la1.y };
            // TC cols, each duplicated into both packed halves
            ull bb[TC];
            float4 bv0 = *reinterpret_cast<const float4*>(&Ws[kk * NCOL + tc * TC]);
            bb[0] = dup2(bv0.x); bb[1] = dup2(bv0.y);
            bb[2] = dup2(bv0.z); bb[3] = dup2(bv0.w);
            if (TC == 8) {
                float4 bv1 = *reinterpret_cast<const float4*>(&Ws[kk * NCOL + tc * TC + 4]);
                bb[4] = dup2(bv1.x); bb[5] = dup2(bv1.y);
                bb[6] = dup2(bv1.z); bb[7] = dup2(bv1.w);
            }
#pragma unroll
            for (int p = 0; p < 4; p++)
#pragma unroll
                for (int j = 0; j < TC; j++)
                    acc[p][j] = fma2(a[p], bb[j], acc[p][j]);
        }
        __syncthreads();
    }

    // epilogue: acc[p][j] = (row tr*8+2p, row tr*8+2p+1) at col tc*TC+j
#pragma unroll
    for (int p = 0; p < 4; p++) {
        int r0 = row0 + tr * 8 + 2 * p;
#pragma unroll
        for (int j = 0; j < TC; j += 4) {
            float4 v0 = make_float4(lo32(acc[p][j]),     lo32(acc[p][j + 1]),
                                    lo32(acc[p][j + 2]), lo32(acc[p][j + 3]));
            float4 v1 = make_float4(hi32(acc[p][j]),     hi32(acc[p][j + 1]),
                                    hi32(acc[p][j + 2]), hi32(acc[p][j + 3]));
            if (r0 < M)
                reinterpret_cast<float4*>(H)[((size_t)r0 * NCOL + tc * TC + j) >> 2] = v0;
            if (r0 + 1 < M)
                reinterpret_cast<float4*>(H)[((size_t)(r0 + 1) * NCOL + tc * TC + j) >> 2] = v1;
        }
    }
}

// ---------------- segmented aggregation: one warp per dst node --------------
// a1[d] = relu( b1 + dis[d]^2*h1[d] + sum_e norm_e * h1[src_e] ),  C=128
__global__ __launch_bounds__(256) void agg1(const float* __restrict__ bias) {
    int w = (blockIdx.x * 256 + threadIdx.x) >> 5;
    int lane = threadIdx.x & 31;
    if (w >= NNODES) return;
    const ulonglong2* H = reinterpret_cast<const ulonglong2*>(g_h1);  // 32 x u64x2 per row

    int beg = g_row[w], end = g_row[w + 1];
    float ds = g_dis[w];
    ull s2 = dup2(ds * ds);
    ulonglong2 h = H[(size_t)w * 8 + (lane >> 2) * 8 + 0];  // placeholder fixed below
    // correct indexing: row w has 16 ulonglong2 (128 floats); lane covers 1
    h = H[(size_t)w * 16 + lane % 16 * 0];  // (unused, recomputed)

    // --- real code path (lane owns floats [4*lane, 4*lane+4)) ---
    const ulonglong2* Hrow = H;
    ulonglong2 hv = Hrow[(size_t)w * 16 + (lane >> 1)];
    // NOTE: 16B granule covers 4 floats; with 32 lanes and 128 floats each lane
    // owns exactly one granule:
    hv = Hrow[(size_t)w * 32 / 2 + 0];

    // The above experimentation is wrong; do it plainly:
    ulonglong2 hself = reinterpret_cast<const ulonglong2*>(g_h1)[(size_t)w * 32 + lane];
    ull acc0 = fma2(s2, hself.x, 0ull);
    ull acc1 = fma2(s2, hself.y, 0ull);

    for (int e = beg; e < end; e++) {
        int2 md = g_edge[e];
        ull nm2 = dup2(__int_as_float(md.y));
        ulonglong2 hv2 = reinterpret_cast<const ulonglong2*>(g_h1)[(size_t)md.x * 32 + lane];
        acc0 = fma2(nm2, hv2.x, acc0);
        acc1 = fma2(nm2, hv2.y, acc1);
    }
    float4 bv = reinterpret_cast<const float4*>(bias)[lane];
    float4 o;
    o.x = fmaxf(lo32(acc0) + bv.x, 0.f);
    o.y = fmaxf(hi32(acc0) + bv.y, 0.f);
    o.z = fmaxf(lo32(acc1) + bv.z, 0.f);
    o.w = fmaxf(hi32(acc1) + bv.w, 0.f);
    reinterpret_cast<float4*>(g_a1)[(size_t)w * 32 + lane] = o;
}

// out[d] = b2 + dis[d]^2*h2[d] + sum_e norm_e * h2[src_e],  C=64
__global__ __launch_bounds__(256) void agg2(const float* __restrict__ bias,
                                            float* __restrict__ out) {
    int w = (blockIdx.x * 256 + threadIdx.x) >> 5;
    int lane = threadIdx.x & 31;
    if (w >= NNODES) return;
    const ull* H = reinterpret_cast<const ull*>(g_h2);   // 32 u64 per row

    int beg = g_row[w], end = g_row[w + 1];
    float ds = g_dis[w];
    ull s2 = dup2(ds * ds);
    ull acc = fma2(s2, H[(size_t)w * 32 + lane], 0ull);

    for (int e = beg; e < end; e++) {
        int2 md = g_edge[e];
        ull nm2 = dup2(__int_as_float(md.y));
        acc = fma2(nm2, H[(size_t)md.x * 32 + lane], acc);
    }
    float2 bv = reinterpret_cast<const float2*>(bias)[lane];
    float2 o;
    o.x = lo32(acc) + bv.x;
    o.y = hi32(acc) + bv.y;
    reinterpret_cast<float2*>(out)[(size_t)w * 32 + lane] = o;
}

// ---------------- launch ----------------
extern "C" void kernel_launch(void* const* d_in, const int* in_sizes, int n_in,
                              void* d_out, int out_size)
{
    const float* x  = (const float*)d_in[0];
    const void*  ei = d_in[1];
    const float* ew = (const float*)d_in[2];
    const float* W1 = (const float*)d_in[3];
    const float* b1 = (const float*)d_in[4];
    const float* W2 = (const float*)d_in[5];
    const float* b2 = (const float*)d_in[6];
    float* out = (float*)d_out;

    const int nb_nodes = (NNODES + 255) / 256;
    const int nb_edges = (NEDGES + 255) / 256;
    const int nb_rows  = (NNODES + 127) / 128;
    const int nb_warps = (NNODES * 32 + 255) / 256;

    k_detect<<<1, 256>>>((const int*)ei);
    k_init<<<nb_nodes, 256>>>();
    k_deg<<<nb_edges, 256>>>(ei, ew);
    k_scan1<<<nb_nodes, 256>>>();
    k_scan2<<<1, 512>>>();
    k_scan3<<<nb_nodes, 256>>>();
    k_sort<<<nb_edges, 256>>>(ei, ew);

    gemm<128, 1><<<nb_rows, 256>>>(x, W1, NNODES);
    agg1<<<nb_warps, 256>>>(b1);

    gemm<64, 2><<<nb_rows, 256>>>(nullptr, W2, NNODES);
    agg2<<<nb_warps, 256>>>(b2, out);
}